// round 2
// baseline (speedup 1.0000x reference)
#include <cuda_runtime.h>
#include <math.h>

#define N_NODES   15000
#define N_EDGES   60000
#define EDGE_VOCAB 54
#define NODE_INDIM 64
#define EDGE_INDIM 32
#define H  32
#define EH 64
#define NBOND 4
#define NUM_STEPS 3

// ---------------- scratch (device globals: no allocation allowed) ----------
__device__ float g_Wv[EDGE_VOCAB * H * H];   // 54 per-vocab edge weight matrices
__device__ float g_h[N_NODES * H];           // node hidden state
__device__ float g_agg[N_NODES * H];         // unnormalized weighted message sum
__device__ float g_p[N_NODES];               // h . attn_w[:H]
__device__ float g_q[N_NODES];               // h . attn_w[H:]
__device__ float g_nmax[N_NODES];            // segment max of logits
__device__ float g_nsum[N_NODES];            // segment sum of exp(logit - max)
__device__ float g_a[N_EDGES];               // per-edge logits

// float atomic max via sign-split int atomics (no CAS loop)
__device__ __forceinline__ void atomicMaxF(float* addr, float v) {
    if (v >= 0.0f) atomicMax((int*)addr, __float_as_int(v));
    else           atomicMin((unsigned int*)addr, __float_as_uint(v));
}

// ---------------- 0) per-vocab edge weight matrices (54 of them) -----------
__global__ void k_wvocab(const float* __restrict__ edge_table,
                         const float* __restrict__ e1W1, const float* __restrict__ e1b1,
                         const float* __restrict__ e1W2, const float* __restrict__ e1b2,
                         const float* __restrict__ e2W1, const float* __restrict__ e2b1,
                         const float* __restrict__ e2W2, const float* __restrict__ e2b2) {
    int v = blockIdx.x;
    bool bond = (v < NBOND);
    const float* W1 = bond ? e1W1 : e2W1;
    const float* b1 = bond ? e1b1 : e2b1;
    const float* W2 = bond ? e1W2 : e2W2;
    const float* b2 = bond ? e1b2 : e2b2;

    __shared__ float ef[EDGE_INDIM];
    __shared__ float z[EH];
    int t = threadIdx.x;                       // 256 threads
    if (t < EDGE_INDIM) ef[t] = edge_table[v * EDGE_INDIM + t];
    __syncthreads();
    if (t < EH) {
        float acc = b1[t];
        #pragma unroll
        for (int i = 0; i < EDGE_INDIM; i++) acc += ef[i] * W1[t * EDGE_INDIM + i];
        z[t] = fmaxf(acc, 0.0f);
    }
    __syncthreads();
    for (int o = t; o < H * H; o += blockDim.x) {
        float acc = b2[o];
        const float* w = W2 + o * EH;
        #pragma unroll
        for (int k = 0; k < EH; k++) acc += z[k] * w[k];
        g_Wv[v * H * H + o] = acc;
    }
}

// ---------------- 1) initial node projection: h = relu(nf @ Wp^T + b) ------
__global__ void k_init_h(const int* __restrict__ node_ids,
                         const float* __restrict__ node_table,
                         const float* __restrict__ projW,
                         const float* __restrict__ projb) {
    __shared__ float sW[NODE_INDIM * H];       // transposed: sW[i*H + o]
    int t = threadIdx.x;
    for (int idx = t; idx < H * NODE_INDIM; idx += blockDim.x) {
        int o = idx / NODE_INDIM, i = idx % NODE_INDIM;
        sW[i * H + o] = projW[idx];
    }
    __syncthreads();
    int gt = blockIdx.x * blockDim.x + t;
    int node = gt >> 5, lane = gt & 31;
    if (node >= N_NODES) return;
    int nid = node_ids[node];
    const float* nf = node_table + nid * NODE_INDIM;
    float v0 = nf[lane];
    float v1 = nf[lane + 32];
    float acc = projb[lane];
    #pragma unroll
    for (int i = 0; i < 32; i++)
        acc += __shfl_sync(0xffffffffu, v0, i) * sW[i * H + lane];
    #pragma unroll
    for (int i = 0; i < 32; i++)
        acc += __shfl_sync(0xffffffffu, v1, i) * sW[(i + 32) * H + lane];
    g_h[node * H + lane] = fmaxf(acc, 0.0f);
}

// ---------------- 2) per-node attention dots + accumulator reset -----------
__global__ void k_node_pre(const float* __restrict__ attn_w) {
    int gt = blockIdx.x * blockDim.x + threadIdx.x;
    int node = gt >> 5, lane = gt & 31;
    if (node >= N_NODES) return;
    float hv = g_h[node * H + lane];
    float pv = hv * attn_w[lane];
    float qv = hv * attn_w[H + lane];
    #pragma unroll
    for (int off = 16; off; off >>= 1) {
        pv += __shfl_down_sync(0xffffffffu, pv, off);
        qv += __shfl_down_sync(0xffffffffu, qv, off);
    }
    if (lane == 0) {
        g_p[node] = pv;
        g_q[node] = qv;
        g_nmax[node] = -3.0e38f;
        g_nsum[node] = 0.0f;
    }
    g_agg[node * H + lane] = 0.0f;
}

// ---------------- 3) edge logits + segment max -----------------------------
__global__ void k_edge_logit(const int* __restrict__ src, const int* __restrict__ dst) {
    int e = blockIdx.x * blockDim.x + threadIdx.x;
    if (e >= N_EDGES) return;
    float a = g_p[src[e]] + g_q[dst[e]];
    a = (a > 0.0f) ? a : 0.01f * a;            // leaky_relu slope 0.01
    g_a[e] = a;
    atomicMaxF(&g_nmax[dst[e]], a);
}

// ---------------- 4) heavy edge kernel: weighted messages (warp/edge) ------
__global__ void k_edge_msg(const int* __restrict__ src, const int* __restrict__ dst,
                           const int* __restrict__ eids) {
    int gt = blockIdx.x * blockDim.x + threadIdx.x;
    int e = gt >> 5, lane = gt & 31;
    if (e >= N_EDGES) return;
    int s = src[e], d = dst[e], id = eids[e];
    float ex = expf(g_a[e] - g_nmax[d]);
    float hv = g_h[s * H + lane];
    const float* __restrict__ W = g_Wv + id * H * H;
    float acc = 0.0f;
    #pragma unroll
    for (int i = 0; i < H; i++)
        acc += __shfl_sync(0xffffffffu, hv, i) * W[i * H + lane];
    if (lane == 0) atomicAdd(&g_nsum[d], ex);
    atomicAdd(&g_agg[d * H + lane], acc * ex);
}

// ---------------- 5) softmax normalize + relu + GRU cell -------------------
__global__ void k_gru(const float* __restrict__ Wih, const float* __restrict__ Whh,
                      const float* __restrict__ bih, const float* __restrict__ bhh,
                      float* __restrict__ out, int writeOut) {
    __shared__ float sWihT[H * 3 * H];         // [i*96 + o]
    __shared__ float sWhhT[H * 3 * H];
    int t = threadIdx.x;
    for (int idx = t; idx < 3 * H * H; idx += blockDim.x) {
        int o = idx / H, i = idx % H;
        sWihT[i * 96 + o] = Wih[idx];
        sWhhT[i * 96 + o] = Whh[idx];
    }
    __syncthreads();
    int gt = blockIdx.x * blockDim.x + t;
    int v = gt >> 5, lane = gt & 31;
    if (v >= N_NODES) return;
    float ns = g_nsum[v];
    float inv = (ns > 0.0f) ? (1.0f / ns) : 0.0f;   // isolated nodes -> m = 0
    float m  = fmaxf(g_agg[v * H + lane] * inv, 0.0f);
    float hv = g_h[v * H + lane];
    float gi0 = bih[lane], gi1 = bih[32 + lane], gi2 = bih[64 + lane];
    float gh0 = bhh[lane], gh1 = bhh[32 + lane], gh2 = bhh[64 + lane];
    #pragma unroll
    for (int i = 0; i < H; i++) {
        float mi = __shfl_sync(0xffffffffu, m, i);
        float hi = __shfl_sync(0xffffffffu, hv, i);
        gi0 += mi * sWihT[i * 96 + lane];
        gi1 += mi * sWihT[i * 96 + 32 + lane];
        gi2 += mi * sWihT[i * 96 + 64 + lane];
        gh0 += hi * sWhhT[i * 96 + lane];
        gh1 += hi * sWhhT[i * 96 + 32 + lane];
        gh2 += hi * sWhhT[i * 96 + 64 + lane];
    }
    float r = 1.0f / (1.0f + expf(-(gi0 + gh0)));
    float z = 1.0f / (1.0f + expf(-(gi1 + gh1)));
    float n = tanhf(gi2 + r * gh2);
    float hnew = (1.0f - z) * n + z * hv;
    g_h[v * H + lane] = hnew;
    if (writeOut) out[v * H + lane] = hnew;
}

// ---------------- launch ----------------------------------------------------
extern "C" void kernel_launch(void* const* d_in, const int* in_sizes, int n_in,
                              void* d_out, int out_size) {
    const int*   node_ids   = (const int*)  d_in[0];
    const int*   edge_ids   = (const int*)  d_in[1];
    const int*   src        = (const int*)  d_in[2];
    const int*   dst        = (const int*)  d_in[3];
    const float* node_table = (const float*)d_in[4];
    const float* edge_table = (const float*)d_in[5];
    const float* proj_W     = (const float*)d_in[6];
    const float* proj_b     = (const float*)d_in[7];
    const float* attn_w     = (const float*)d_in[8];
    const float* e1_W1      = (const float*)d_in[9];
    const float* e1_b1      = (const float*)d_in[10];
    const float* e1_W2      = (const float*)d_in[11];
    const float* e1_b2      = (const float*)d_in[12];
    const float* e2_W1      = (const float*)d_in[13];
    const float* e2_b1      = (const float*)d_in[14];
    const float* e2_W2      = (const float*)d_in[15];
    const float* e2_b2      = (const float*)d_in[16];
    const float* gru_Wih    = (const float*)d_in[17];
    const float* gru_Whh    = (const float*)d_in[18];
    const float* gru_bih    = (const float*)d_in[19];
    const float* gru_bhh    = (const float*)d_in[20];
    float* out = (float*)d_out;

    const int NODE_WARP_BLOCKS = (N_NODES * 32 + 255) / 256;   // warp per node
    const int EDGE_WARP_BLOCKS = (N_EDGES * 32 + 255) / 256;   // warp per edge
    const int EDGE_THR_BLOCKS  = (N_EDGES + 255) / 256;        // thread per edge

    k_wvocab<<<EDGE_VOCAB, 256>>>(edge_table, e1_W1, e1_b1, e1_W2, e1_b2,
                                  e2_W1, e2_b1, e2_W2, e2_b2);
    k_init_h<<<NODE_WARP_BLOCKS, 256>>>(node_ids, node_table, proj_W, proj_b);

    for (int step = 0; step < NUM_STEPS; step++) {
        k_node_pre<<<NODE_WARP_BLOCKS, 256>>>(attn_w);
        k_edge_logit<<<EDGE_THR_BLOCKS, 256>>>(src, dst);
        k_edge_msg<<<EDGE_WARP_BLOCKS, 256>>>(src, dst, edge_ids);
        k_gru<<<NODE_WARP_BLOCKS, 256>>>(gru_Wih, gru_Whh, gru_bih, gru_bhh,
                                         out, step == NUM_STEPS - 1 ? 1 : 0);
    }
}